// round 6
// baseline (speedup 1.0000x reference)
#include <cuda_runtime.h>
#include <cuda_bf16.h>
#include <stdint.h>

// ---------------- problem constants ----------------
#define NUM_EXEC   50
#define MAXB       60000
#define MAXT       (MAXB * NUM_EXEC)

typedef unsigned long long ull;

// ---------------- device scratch ----------------
__device__ int   g_nsel[MAXB];
__device__ int   g_blocksum[512];
__device__ int   g_rowjob[MAXT];
__device__ float g_base1[(size_t)MAXB * 64];
// prepped weight blob (exact smem image):
//  [0,8192)      W2^T hi  bf16 [n=64][k=64], 128B rows, XOR-16B swizzle
//  [8192,16384)  W2^T lo
//  [16384,20480) W3^T hi  [n=32][k=64]
//  [20480,24576) W3^T lo
//  [24576,25600) fp32 smalls: W1L[64] b2[64] b3[32] W4[32] b4[1]
__device__ __align__(16) unsigned char g_wblob[25600];

// ---------------- helpers ----------------
__device__ __forceinline__ ull fma2(ull a, ull b, ull c) {
    ull d;
    asm("fma.rn.f32x2 %0, %1, %2, %3;" : "=l"(d) : "l"(a), "l"(b), "l"(c));
    return d;
}
__device__ __forceinline__ ull pack2(float a, float b) {
    ull r;
    asm("mov.b64 %0, {%1,%2};" : "=l"(r) : "f"(a), "f"(b));
    return r;
}
__device__ __forceinline__ void unpack2(ull v, float& a, float& b) {
    asm("mov.b64 {%0,%1}, %2;" : "=f"(a), "=f"(b) : "l"(v));
}
__device__ __forceinline__ uint32_t smem_u32(const void* p) {
    uint32_t a;
    asm("{ .reg .u64 t; cvta.to.shared.u64 t, %1; cvt.u32.u64 %0, t; }" : "=r"(a) : "l"(p));
    return a;
}
// pack (lo_elem, hi_elem) -> bf16x2, lo_elem in low 16 bits
__device__ __forceinline__ uint32_t packbf2(float lov, float hiv) {
    uint32_t r;
    asm("cvt.rn.bf16x2.f32 %0, %1, %2;" : "=r"(r) : "f"(hiv), "f"(lov));
    return r;
}
__device__ __forceinline__ void ldmatrix4(uint32_t& a0, uint32_t& a1, uint32_t& a2,
                                          uint32_t& a3, uint32_t addr) {
    asm volatile("ldmatrix.sync.aligned.m8n8.x4.shared.b16 {%0,%1,%2,%3}, [%4];"
                 : "=r"(a0), "=r"(a1), "=r"(a2), "=r"(a3) : "r"(addr));
}
__device__ __forceinline__ void mma16816(float& d0, float& d1, float& d2, float& d3,
                                         uint32_t a0, uint32_t a1, uint32_t a2, uint32_t a3,
                                         uint32_t b0, uint32_t b1) {
    asm volatile("mma.sync.aligned.m16n8k16.row.col.f32.bf16.bf16.f32 "
                 "{%0,%1,%2,%3}, {%4,%5,%6,%7}, {%8,%9}, {%0,%1,%2,%3};"
                 : "+f"(d0), "+f"(d1), "+f"(d2), "+f"(d3)
                 : "r"(a0), "r"(a1), "r"(a2), "r"(a3), "r"(b0), "r"(b1));
}
// XOR-16B swizzle for 128B rows: byte ^ ((byte>>3)&0x70)
__device__ __host__ __forceinline__ uint32_t sw128(uint32_t b) {
    return b ^ ((b >> 3) & 0x70);
}

// ================= prologue 1: nsel gather + per-256 block sums =================
__global__ void k_p1(const int* __restrict__ job_indices,
                     const int* __restrict__ num_exec_acts, int J) {
    __shared__ int s[256];
    int j = blockIdx.x * 256 + threadIdx.x;
    int v = 0;
    if (j < J) { v = num_exec_acts[job_indices[j]]; g_nsel[j] = v; }
    s[threadIdx.x] = v;
    __syncthreads();
    #pragma unroll
    for (int o = 128; o > 0; o >>= 1) {
        if (threadIdx.x < o) s[threadIdx.x] += s[threadIdx.x + o];
        __syncthreads();
    }
    if (threadIdx.x == 0) g_blocksum[blockIdx.x] = s[0];
}

// ================= prologue 2: exclusive scan of block sums =================
__global__ void k_scan(int nblocks) {
    __shared__ int s[512];
    int tid = threadIdx.x;
    int v = (tid < nblocks) ? g_blocksum[tid] : 0;
    s[tid] = v;
    __syncthreads();
    for (int o = 1; o < 512; o <<= 1) {
        int t = (tid >= o) ? s[tid - o] : 0;
        __syncthreads();
        s[tid] += t;
        __syncthreads();
    }
    if (tid < nblocks) g_blocksum[tid] = s[tid] - v;
}

// ================= prologue 3: per-job start + row->job fill =================
__global__ void k_p3(int J) {
    __shared__ int s[256];
    int tid = threadIdx.x;
    int j = blockIdx.x * 256 + tid;
    int v = (j < J) ? g_nsel[j] : 0;
    s[tid] = v;
    __syncthreads();
    for (int o = 1; o < 256; o <<= 1) {
        int t = (tid >= o) ? s[tid - o] : 0;
        __syncthreads();
        s[tid] += t;
        __syncthreads();
    }
    if (j < J) {
        int start = (s[tid] - v) + g_blocksum[blockIdx.x];
        for (int k = 0; k < v; k++) g_rowjob[start + k] = j;
    }
}

// ================= prologue 4: base1 = in35 @ W1[:35] + b1 (fp32) =================
__global__ void __launch_bounds__(256) k_base1(
    const float* __restrict__ x, const float* __restrict__ h_dag,
    const float* __restrict__ h_glob,
    const int* __restrict__ ptr, const int* __restrict__ jidx,
    const float* __restrict__ W1, const float* __restrict__ b1, int J) {
    __shared__ __align__(16) float sW1[35 * 64];
    __shared__ __align__(16) float sB1[64];
    for (int i = threadIdx.x; i < 35 * 64; i += blockDim.x) sW1[i] = W1[i];
    for (int i = threadIdx.x; i < 64; i += blockDim.x)      sB1[i] = b1[i];
    __syncthreads();

    int j = blockIdx.x * 8 + (threadIdx.x >> 5);
    int lane = threadIdx.x & 31;
    if (j >= J) return;

    int ji = jidx[j];
    long long node = (long long)ptr[ji];
    const float* xr = x + node * 5;
    const float4* hd = (const float4*)(h_dag + (long long)ji * 16);
    const float4* hg = (const float4*)(h_glob + (long long)j * 16);

    // batch all input loads up-front (broadcast across lanes, MLP ~11)
    float v[35];
    v[0] = xr[0]; v[1] = xr[1]; v[2] = xr[2];
    #pragma unroll
    for (int q = 0; q < 4; q++) {
        float4 a = hd[q];
        v[3 + 4 * q + 0] = a.x; v[3 + 4 * q + 1] = a.y;
        v[3 + 4 * q + 2] = a.z; v[3 + 4 * q + 3] = a.w;
    }
    #pragma unroll
    for (int q = 0; q < 4; q++) {
        float4 a = hg[q];
        v[19 + 4 * q + 0] = a.x; v[19 + 4 * q + 1] = a.y;
        v[19 + 4 * q + 2] = a.z; v[19 + 4 * q + 3] = a.w;
    }

    ull acc = pack2(sB1[2 * lane], sB1[2 * lane + 1]);
    #pragma unroll
    for (int i = 0; i < 35; i++)
        acc = fma2(pack2(v[i], v[i]), *(const ull*)&sW1[i * 64 + 2 * lane], acc);

    float a, b;
    unpack2(acc, a, b);
    float* dst = g_base1 + (size_t)j * 64 + 2 * lane;
    dst[0] = a;
    dst[1] = b;
}

// ================= prologue 5: weight prep (transpose + bf16 split + swizzle) =====
__global__ void k_wprep(const float* __restrict__ W1, const float* __restrict__ W2,
                        const float* __restrict__ b2, const float* __restrict__ W3,
                        const float* __restrict__ b3, const float* __restrict__ W4,
                        const float* __restrict__ b4) {
    int tid = blockIdx.x * blockDim.x + threadIdx.x;
    if (tid < 4096) {                 // W2^T: [n][k] = W2[k][n]
        int n = tid >> 6, k = tid & 63;
        float w = W2[k * 64 + n];
        __nv_bfloat16 h = __float2bfloat16_rn(w);
        float r = w - __bfloat162float(h);
        __nv_bfloat16 l = __float2bfloat16_rn(r);
        uint32_t sw = sw128((uint32_t)(n * 128 + 2 * k));
        *(__nv_bfloat16*)(g_wblob + sw)        = h;
        *(__nv_bfloat16*)(g_wblob + 8192 + sw) = l;
    } else if (tid < 6144) {          // W3^T: [n][k] = W3[k][n]
        int e = tid - 4096;
        int n = e >> 6, k = e & 63;
        float w = W3[k * 32 + n];
        __nv_bfloat16 h = __float2bfloat16_rn(w);
        float r = w - __bfloat162float(h);
        __nv_bfloat16 l = __float2bfloat16_rn(r);
        uint32_t sw = sw128((uint32_t)(n * 128 + 2 * k));
        *(__nv_bfloat16*)(g_wblob + 16384 + sw) = h;
        *(__nv_bfloat16*)(g_wblob + 20480 + sw) = l;
    } else if (tid < 6144 + 256) {
        int i = tid - 6144;
        float* s = (float*)(g_wblob + 24576);
        if (i < 64)       s[i] = W1[35 * 64 + i];
        else if (i < 128) s[i] = b2[i - 64];
        else if (i < 160) s[i] = b3[i - 128];
        else if (i < 192) s[i] = W4[i - 160];
        else if (i == 192) s[192] = b4[0];
    }
}

// ================= main: persistent mma.sync fused MLP =================
// dyn smem: [0,25600) weight blob image; [25600,41984) A_hi [128][128B] swizzled;
//           [41984,58368) A_lo
#define SM_AHI 25600
#define SM_ALO 41984
#define KM_SMEM 58368

__global__ void __launch_bounds__(128, 3) k_mlp_mma(
    const int* __restrict__ exec_act_idx, float* __restrict__ out, int T, int ntiles) {

    extern __shared__ unsigned char sm8[];
    const uint32_t smb = smem_u32(sm8);
    const float* smallf = (const float*)(sm8 + 24576);

    const int tid  = threadIdx.x;
    const int warp = tid >> 5;
    const int lane = tid & 31;
    const int q    = lane & 3;        // quad index
    const int qr   = lane >> 2;       // row-within-8
    const int rbase = warp * 32;

    // ---- copy prepped weights + smalls (25600 B), ONCE per CTA ----
    {
        const uint4* src = (const uint4*)g_wblob;
        uint4* dst = (uint4*)sm8;
        #pragma unroll
        for (int it = 0; it < 13; it++) {
            int i = tid + it * 128;
            if (i < 1600) dst[i] = src[i];
        }
    }

    for (int tile = blockIdx.x; tile < ntiles; tile += gridDim.x) {
        __syncthreads();   // weights ready (1st iter); prev iter's A reads done

        const int t  = tile * 128 + tid;
        const int tt = (t < T) ? t : (T - 1);

        // ---- layer 1: h1 = relu(base1[j] + kf*W1L) -> bf16 hi/lo -> smem A ----
        {
            int j   = g_rowjob[tt];
            float kf = (float)exec_act_idx[tt] * (1.0f / (float)NUM_EXEC);
            const float4* bp = (const float4*)(g_base1 + (size_t)j * 64);
            const int row = tid;
            #pragma unroll
            for (int c = 0; c < 8; c++) {               // 8 elems per 16B chunk
                float4 va = bp[2 * c];
                float4 vb = bp[2 * c + 1];
                float v[8] = {
                    fmaxf(fmaf(kf, smallf[8 * c + 0], va.x), 0.0f),
                    fmaxf(fmaf(kf, smallf[8 * c + 1], va.y), 0.0f),
                    fmaxf(fmaf(kf, smallf[8 * c + 2], va.z), 0.0f),
                    fmaxf(fmaf(kf, smallf[8 * c + 3], va.w), 0.0f),
                    fmaxf(fmaf(kf, smallf[8 * c + 4], vb.x), 0.0f),
                    fmaxf(fmaf(kf, smallf[8 * c + 5], vb.y), 0.0f),
                    fmaxf(fmaf(kf, smallf[8 * c + 6], vb.z), 0.0f),
                    fmaxf(fmaf(kf, smallf[8 * c + 7], vb.w), 0.0f)};
                uint32_t hw[4], lw[4];
                #pragma unroll
                for (int p = 0; p < 4; p++) {
                    uint32_t hp = packbf2(v[2 * p], v[2 * p + 1]);
                    float r0 = v[2 * p]     - __uint_as_float(hp << 16);
                    float r1 = v[2 * p + 1] - __uint_as_float(hp & 0xFFFF0000u);
                    hw[p] = hp;
                    lw[p] = packbf2(r0, r1);
                }
                uint32_t off = row * 128 + ((c ^ (row & 7)) << 4);
                *(uint4*)(sm8 + SM_AHI + off) = make_uint4(hw[0], hw[1], hw[2], hw[3]);
                *(uint4*)(sm8 + SM_ALO + off) = make_uint4(lw[0], lw[1], lw[2], lw[3]);
            }
        }
        __syncthreads();

        // ---- layer 2: C[128,64] = A(hi/lo) @ W2T(hi/lo), 3 split products ----
        float acc2[2][8][4];
        #pragma unroll
        for (int mt = 0; mt < 2; mt++)
            #pragma unroll
            for (int nt = 0; nt < 8; nt++)
                #pragma unroll
                for (int e = 0; e < 4; e++) acc2[mt][nt][e] = 0.0f;

        #pragma unroll
        for (int kt = 0; kt < 4; kt++) {
            uint32_t ah[2][4], al[2][4];
            #pragma unroll
            for (int mt = 0; mt < 2; mt++) {
                int r = rbase + mt * 16 + (lane & 15);
                uint32_t cb = kt * 32 + ((lane >> 4) << 4);
                uint32_t off = r * 128 + (cb ^ ((r & 7) << 4));
                ldmatrix4(ah[mt][0], ah[mt][1], ah[mt][2], ah[mt][3], smb + SM_AHI + off);
                ldmatrix4(al[mt][0], al[mt][1], al[mt][2], al[mt][3], smb + SM_ALO + off);
            }
            #pragma unroll
            for (int nt = 0; nt < 8; nt++) {
                int n = nt * 8 + qr;
                uint32_t byte0 = n * 128 + kt * 32 + 4 * q;
                uint32_t o0 = sw128(byte0), o1 = sw128(byte0 + 16);
                uint32_t bh0 = *(const uint32_t*)(sm8 + o0);
                uint32_t bh1 = *(const uint32_t*)(sm8 + o1);
                uint32_t bl0 = *(const uint32_t*)(sm8 + 8192 + o0);
                uint32_t bl1 = *(const uint32_t*)(sm8 + 8192 + o1);
                #pragma unroll
                for (int mt = 0; mt < 2; mt++) {
                    float* d = acc2[mt][nt];
                    mma16816(d[0], d[1], d[2], d[3], ah[mt][0], ah[mt][1], ah[mt][2], ah[mt][3], bh0, bh1);
                    mma16816(d[0], d[1], d[2], d[3], ah[mt][0], ah[mt][1], ah[mt][2], ah[mt][3], bl0, bl1);
                    mma16816(d[0], d[1], d[2], d[3], al[mt][0], al[mt][1], al[mt][2], al[mt][3], bh0, bh1);
                }
            }
        }
        __syncthreads();   // all A reads done before overwrite

        // ---- epilogue L2: h2 = relu(C + b2) -> bf16 hi/lo -> smem A ----
        #pragma unroll
        for (int mt = 0; mt < 2; mt++) {
            int r0 = rbase + mt * 16 + qr;
            #pragma unroll
            for (int nt = 0; nt < 8; nt++) {
                int cn = nt * 8 + 2 * q;
                float bb0 = smallf[64 + cn], bb1 = smallf[64 + cn + 1];
                float v0 = fmaxf(acc2[mt][nt][0] + bb0, 0.0f);
                float v1 = fmaxf(acc2[mt][nt][1] + bb1, 0.0f);
                float v2 = fmaxf(acc2[mt][nt][2] + bb0, 0.0f);
                float v3 = fmaxf(acc2[mt][nt][3] + bb1, 0.0f);
                uint32_t h01 = packbf2(v0, v1);
                uint32_t l01 = packbf2(v0 - __uint_as_float(h01 << 16),
                                       v1 - __uint_as_float(h01 & 0xFFFF0000u));
                uint32_t h23 = packbf2(v2, v3);
                uint32_t l23 = packbf2(v2 - __uint_as_float(h23 << 16),
                                       v3 - __uint_as_float(h23 & 0xFFFF0000u));
                uint32_t oa = sw128((uint32_t)(r0 * 128 + cn * 2));
                uint32_t ob = sw128((uint32_t)((r0 + 8) * 128 + cn * 2));
                *(uint32_t*)(sm8 + SM_AHI + oa) = h01;
                *(uint32_t*)(sm8 + SM_ALO + oa) = l01;
                *(uint32_t*)(sm8 + SM_AHI + ob) = h23;
                *(uint32_t*)(sm8 + SM_ALO + ob) = l23;
            }
        }
        __syncthreads();

        // ---- layer 3: C[128,32] = A @ W3T ----
        float acc3[2][4][4];
        #pragma unroll
        for (int mt = 0; mt < 2; mt++)
            #pragma unroll
            for (int nt = 0; nt < 4; nt++)
                #pragma unroll
                for (int e = 0; e < 4; e++) acc3[mt][nt][e] = 0.0f;

        #pragma unroll
        for (int kt = 0; kt < 4; kt++) {
            uint32_t ah[2][4], al[2][4];
            #pragma unroll
            for (int mt = 0; mt < 2; mt++) {
                int r = rbase + mt * 16 + (lane & 15);
                uint32_t cb = kt * 32 + ((lane >> 4) << 4);
                uint32_t off = r * 128 + (cb ^ ((r & 7) << 4));
                ldmatrix4(ah[mt][0], ah[mt][1], ah[mt][2], ah[mt][3], smb + SM_AHI + off);
                ldmatrix4(al[mt][0], al[mt][1], al[mt][2], al[mt][3], smb + SM_ALO + off);
            }
            #pragma unroll
            for (int nt = 0; nt < 4; nt++) {
                int n = nt * 8 + qr;
                uint32_t byte0 = n * 128 + kt * 32 + 4 * q;
                uint32_t o0 = sw128(byte0), o1 = sw128(byte0 + 16);
                uint32_t bh0 = *(const uint32_t*)(sm8 + 16384 + o0);
                uint32_t bh1 = *(const uint32_t*)(sm8 + 16384 + o1);
                uint32_t bl0 = *(const uint32_t*)(sm8 + 20480 + o0);
                uint32_t bl1 = *(const uint32_t*)(sm8 + 20480 + o1);
                #pragma unroll
                for (int mt = 0; mt < 2; mt++) {
                    float* d = acc3[mt][nt];
                    mma16816(d[0], d[1], d[2], d[3], ah[mt][0], ah[mt][1], ah[mt][2], ah[mt][3], bh0, bh1);
                    mma16816(d[0], d[1], d[2], d[3], ah[mt][0], ah[mt][1], ah[mt][2], ah[mt][3], bl0, bl1);
                    mma16816(d[0], d[1], d[2], d[3], al[mt][0], al[mt][1], al[mt][2], al[mt][3], bh0, bh1);
                }
            }
        }

        // ---- epilogue L3: relu(C + b3) . W4, quad reduce, write ----
        #pragma unroll
        for (int mt = 0; mt < 2; mt++) {
            float sa = 0.0f, sb = 0.0f;
            #pragma unroll
            for (int nt = 0; nt < 4; nt++) {
                int cn = nt * 8 + 2 * q;
                float b0 = smallf[128 + cn], b1 = smallf[128 + cn + 1];
                float w0 = smallf[160 + cn], w1 = smallf[160 + cn + 1];
                sa = fmaf(fmaxf(acc3[mt][nt][0] + b0, 0.0f), w0, sa);
                sa = fmaf(fmaxf(acc3[mt][nt][1] + b1, 0.0f), w1, sa);
                sb = fmaf(fmaxf(acc3[mt][nt][2] + b0, 0.0f), w0, sb);
                sb = fmaf(fmaxf(acc3[mt][nt][3] + b1, 0.0f), w1, sb);
            }
            sa += __shfl_xor_sync(0xFFFFFFFFu, sa, 1);
            sa += __shfl_xor_sync(0xFFFFFFFFu, sa, 2);
            sb += __shfl_xor_sync(0xFFFFFFFFu, sb, 1);
            sb += __shfl_xor_sync(0xFFFFFFFFu, sb, 2);
            if (q == 0) {
                int ra = tile * 128 + rbase + mt * 16 + qr;
                float b4v = smallf[192];
                if (ra < T)     out[ra]     = sa + b4v;
                if (ra + 8 < T) out[ra + 8] = sb + b4v;
            }
        }
    }
}

// ================= launcher =================
extern "C" void kernel_launch(void* const* d_in, const int* in_sizes, int n_in,
                              void* d_out, int out_size) {
    const float* x          = (const float*)d_in[0];
    const float* h_dag      = (const float*)d_in[1];
    const float* h_glob     = (const float*)d_in[2];
    const int* ptr          = (const int*)d_in[3];
    const int* job_idx      = (const int*)d_in[4];
    const int* num_exec     = (const int*)d_in[5];
    const int* exec_aidx    = (const int*)d_in[6];
    const float* W1 = (const float*)d_in[7];
    const float* b1 = (const float*)d_in[8];
    const float* W2 = (const float*)d_in[9];
    const float* b2 = (const float*)d_in[10];
    const float* W3 = (const float*)d_in[11];
    const float* b3 = (const float*)d_in[12];
    const float* W4 = (const float*)d_in[13];
    const float* b4 = (const float*)d_in[14];
    float* out = (float*)d_out;

    int J = in_sizes[4];
    int T = in_sizes[6];

    cudaFuncSetAttribute(k_mlp_mma, cudaFuncAttributeMaxDynamicSharedMemorySize, KM_SMEM);

    int nblocks256 = (J + 255) / 256;
    int ntiles = (T + 127) / 128;
    int grid = 148 * 3;
    if (grid > ntiles) grid = ntiles;

    k_p1<<<nblocks256, 256>>>(job_idx, num_exec, J);
    k_scan<<<1, 512>>>(nblocks256);
    k_p3<<<nblocks256, 256>>>(J);
    k_base1<<<(J + 7) / 8, 256>>>(x, h_dag, h_glob, ptr, job_idx, W1, b1, J);
    k_wprep<<<25, 256>>>(W1, W2, b2, W3, b3, W4, b4);
    k_mlp_mma<<<grid, 128, KM_SMEM>>>(exec_aidx, out, T, ntiles);
}

// round 7
// speedup vs baseline: 1.3627x; 1.3627x over previous
#include <cuda_runtime.h>
#include <cuda_fp16.h>
#include <stdint.h>

// ---------------- problem constants ----------------
#define NUM_EXEC   50
#define MAXB       60000
#define MAXT       (MAXB * NUM_EXEC)

typedef unsigned long long ull;

// ---------------- device scratch ----------------
__device__ int   g_nsel[MAXB];
__device__ int   g_blocksum[512];
__device__ int   g_rowjob[MAXT];
__device__ float g_base1[(size_t)MAXB * 64];
// prepped weight blob (exact smem image):
//  [0,8192)      W2^T hi  fp16 [n=64][k=64], 128B rows, XOR-16B swizzle
//  [8192,16384)  W2^T lo  (fp16 residual)
//  [16384,20480) W3^T hi  [n=32][k=64]
//  [20480,24576) W3^T lo
//  [24576,25600) fp32 smalls: W1L[64] b2[64] b3[32] W4[32] b4[1]
__device__ __align__(16) unsigned char g_wblob[25600];

// ---------------- helpers ----------------
__device__ __forceinline__ ull fma2(ull a, ull b, ull c) {
    ull d;
    asm("fma.rn.f32x2 %0, %1, %2, %3;" : "=l"(d) : "l"(a), "l"(b), "l"(c));
    return d;
}
__device__ __forceinline__ ull pack2(float a, float b) {
    ull r;
    asm("mov.b64 %0, {%1,%2};" : "=l"(r) : "f"(a), "f"(b));
    return r;
}
__device__ __forceinline__ void unpack2(ull v, float& a, float& b) {
    asm("mov.b64 {%0,%1}, %2;" : "=f"(a), "=f"(b) : "l"(v));
}
__device__ __forceinline__ uint32_t smem_u32(const void* p) {
    uint32_t a;
    asm("{ .reg .u64 t; cvta.to.shared.u64 t, %1; cvt.u32.u64 %0, t; }" : "=r"(a) : "l"(p));
    return a;
}
// pack (lo_elem, hi_elem) -> f16x2, lo_elem in low 16 bits
__device__ __forceinline__ uint32_t packh2(float lov, float hiv) {
    uint32_t r;
    asm("cvt.rn.f16x2.f32 %0, %1, %2;" : "=r"(r) : "f"(hiv), "f"(lov));
    return r;
}
__device__ __forceinline__ void ldmatrix4(uint32_t& a0, uint32_t& a1, uint32_t& a2,
                                          uint32_t& a3, uint32_t addr) {
    asm volatile("ldmatrix.sync.aligned.m8n8.x4.shared.b16 {%0,%1,%2,%3}, [%4];"
                 : "=r"(a0), "=r"(a1), "=r"(a2), "=r"(a3) : "r"(addr));
}
__device__ __forceinline__ void mma16816(float& d0, float& d1, float& d2, float& d3,
                                         uint32_t a0, uint32_t a1, uint32_t a2, uint32_t a3,
                                         uint32_t b0, uint32_t b1) {
    asm volatile("mma.sync.aligned.m16n8k16.row.col.f32.f16.f16.f32 "
                 "{%0,%1,%2,%3}, {%4,%5,%6,%7}, {%8,%9}, {%0,%1,%2,%3};"
                 : "+f"(d0), "+f"(d1), "+f"(d2), "+f"(d3)
                 : "r"(a0), "r"(a1), "r"(a2), "r"(a3), "r"(b0), "r"(b1));
}
// XOR-16B swizzle for 128B rows
__device__ __host__ __forceinline__ uint32_t sw128(uint32_t b) {
    return b ^ ((b >> 3) & 0x70);
}

// ================= prologue 1: nsel gather + per-256 block sums =================
__global__ void k_p1(const int* __restrict__ job_indices,
                     const int* __restrict__ num_exec_acts, int J) {
    __shared__ int s[256];
    int j = blockIdx.x * 256 + threadIdx.x;
    int v = 0;
    if (j < J) { v = num_exec_acts[job_indices[j]]; g_nsel[j] = v; }
    s[threadIdx.x] = v;
    __syncthreads();
    #pragma unroll
    for (int o = 128; o > 0; o >>= 1) {
        if (threadIdx.x < o) s[threadIdx.x] += s[threadIdx.x + o];
        __syncthreads();
    }
    if (threadIdx.x == 0) g_blocksum[blockIdx.x] = s[0];
}

// ================= prologue 2: exclusive scan of block sums =================
__global__ void k_scan(int nblocks) {
    __shared__ int s[512];
    int tid = threadIdx.x;
    int v = (tid < nblocks) ? g_blocksum[tid] : 0;
    s[tid] = v;
    __syncthreads();
    for (int o = 1; o < 512; o <<= 1) {
        int t = (tid >= o) ? s[tid - o] : 0;
        __syncthreads();
        s[tid] += t;
        __syncthreads();
    }
    if (tid < nblocks) g_blocksum[tid] = s[tid] - v;
}

// ================= prologue 3: per-job start + row->job fill =================
__global__ void k_p3(int J) {
    __shared__ int s[256];
    int tid = threadIdx.x;
    int j = blockIdx.x * 256 + tid;
    int v = (j < J) ? g_nsel[j] : 0;
    s[tid] = v;
    __syncthreads();
    for (int o = 1; o < 256; o <<= 1) {
        int t = (tid >= o) ? s[tid - o] : 0;
        __syncthreads();
        s[tid] += t;
        __syncthreads();
    }
    if (j < J) {
        int start = (s[tid] - v) + g_blocksum[blockIdx.x];
        for (int k = 0; k < v; k++) g_rowjob[start + k] = j;
    }
}

// ================= prologue 4: base1 (PERSISTENT: stage W1 once, loop jobs) ==========
__global__ void __launch_bounds__(256) k_base1(
    const float* __restrict__ x, const float* __restrict__ h_dag,
    const float* __restrict__ h_glob,
    const int* __restrict__ ptr, const int* __restrict__ jidx,
    const float* __restrict__ W1, const float* __restrict__ b1, int J) {
    __shared__ __align__(16) float sW1[35 * 64];
    __shared__ __align__(16) float sB1[64];
    for (int i = threadIdx.x; i < 35 * 64; i += blockDim.x) sW1[i] = W1[i];
    for (int i = threadIdx.x; i < 64; i += blockDim.x)      sB1[i] = b1[i];
    __syncthreads();

    const int warp = threadIdx.x >> 5;
    const int lane = threadIdx.x & 31;
    const int stride = gridDim.x * 8;

    for (int j = blockIdx.x * 8 + warp; j < J; j += stride) {
        int ji = jidx[j];
        long long node = (long long)ptr[ji];
        const float* xr = x + node * 5;
        const float4* hd = (const float4*)(h_dag + (long long)ji * 16);
        const float4* hg = (const float4*)(h_glob + (long long)j * 16);

        float v[35];
        v[0] = xr[0]; v[1] = xr[1]; v[2] = xr[2];
        #pragma unroll
        for (int q = 0; q < 4; q++) {
            float4 a = hd[q];
            v[3 + 4 * q + 0] = a.x; v[3 + 4 * q + 1] = a.y;
            v[3 + 4 * q + 2] = a.z; v[3 + 4 * q + 3] = a.w;
        }
        #pragma unroll
        for (int q = 0; q < 4; q++) {
            float4 a = hg[q];
            v[19 + 4 * q + 0] = a.x; v[19 + 4 * q + 1] = a.y;
            v[19 + 4 * q + 2] = a.z; v[19 + 4 * q + 3] = a.w;
        }

        ull acc = pack2(sB1[2 * lane], sB1[2 * lane + 1]);
        #pragma unroll
        for (int i = 0; i < 35; i++)
            acc = fma2(pack2(v[i], v[i]), *(const ull*)&sW1[i * 64 + 2 * lane], acc);

        float a, b;
        unpack2(acc, a, b);
        float* dst = g_base1 + (size_t)j * 64 + 2 * lane;
        dst[0] = a;
        dst[1] = b;
    }
}

// ================= prologue 5: weight prep (transpose + fp16 split + swizzle) =====
__global__ void k_wprep(const float* __restrict__ W1, const float* __restrict__ W2,
                        const float* __restrict__ b2, const float* __restrict__ W3,
                        const float* __restrict__ b3, const float* __restrict__ W4,
                        const float* __restrict__ b4) {
    int tid = blockIdx.x * blockDim.x + threadIdx.x;
    if (tid < 4096) {                 // W2^T: [n][k] = W2[k][n]
        int n = tid >> 6, k = tid & 63;
        float w = W2[k * 64 + n];
        __half h = __float2half_rn(w);
        __half l = __float2half_rn(w - __half2float(h));
        uint32_t sw = sw128((uint32_t)(n * 128 + 2 * k));
        *(__half*)(g_wblob + sw)        = h;
        *(__half*)(g_wblob + 8192 + sw) = l;
    } else if (tid < 6144) {          // W3^T: [n][k] = W3[k][n]
        int e = tid - 4096;
        int n = e >> 6, k = e & 63;
        float w = W3[k * 32 + n];
        __half h = __float2half_rn(w);
        __half l = __float2half_rn(w - __half2float(h));
        uint32_t sw = sw128((uint32_t)(n * 128 + 2 * k));
        *(__half*)(g_wblob + 16384 + sw) = h;
        *(__half*)(g_wblob + 20480 + sw) = l;
    } else if (tid < 6144 + 256) {
        int i = tid - 6144;
        float* s = (float*)(g_wblob + 24576);
        if (i < 64)       s[i] = W1[35 * 64 + i];
        else if (i < 128) s[i] = b2[i - 64];
        else if (i < 160) s[i] = b3[i - 128];
        else if (i < 192) s[i] = W4[i - 160];
        else if (i == 192) s[192] = b4[0];
    }
}

// ================= main: mma.sync (fp16 2-product) fused MLP, 128 rows/CTA ==========
// dyn smem: [0,25600) weight blob image; [25600,41984) A fp16 [128][128B] swizzled
#define SM_A    25600
#define KM_SMEM 41984

__global__ void __launch_bounds__(128, 4) k_mlp_mma(
    const int* __restrict__ exec_act_idx, float* __restrict__ out, int T) {

    extern __shared__ unsigned char sm8[];
    const uint32_t smb = smem_u32(sm8);
    const float* smallf = (const float*)(sm8 + 24576);

    const int tid  = threadIdx.x;
    const int warp = tid >> 5;
    const int lane = tid & 31;
    const int q    = lane & 3;        // quad index
    const int qr   = lane >> 2;       // row-within-8
    const int rbase = warp * 32;

    // ---- copy prepped weights + smalls (25600 B) ----
    {
        const uint4* src = (const uint4*)g_wblob;
        uint4* dst = (uint4*)sm8;
        #pragma unroll
        for (int it = 0; it < 13; it++) {
            int i = tid + it * 128;
            if (i < 1600) dst[i] = src[i];
        }
    }
    __syncthreads();

    const int t  = blockIdx.x * 128 + tid;
    const int tt = (t < T) ? t : (T - 1);

    // ---- layer 1: h1 = relu(base1[j] + kf*W1L) -> fp16 -> smem A ----
    {
        int j   = g_rowjob[tt];
        float kf = (float)exec_act_idx[tt] * (1.0f / (float)NUM_EXEC);
        const float4* bp = (const float4*)(g_base1 + (size_t)j * 64);
        const int row = tid;
        #pragma unroll
        for (int c = 0; c < 4; c++) {               // 16 elems per 16B fp16 chunk? no: 8 fp16 = 16B
            // each iteration writes one 16B chunk = 8 fp16 values
            // process two chunks per c? -> unroll over 8 chunks of 8 values
        }
        #pragma unroll
        for (int c = 0; c < 8; c++) {               // 8 chunks x 8 values = 64
            float4 va = bp[2 * c];
            float4 vb = bp[2 * c + 1];
            float v0 = fmaxf(fmaf(kf, smallf[8 * c + 0], va.x), 0.0f);
            float v1 = fmaxf(fmaf(kf, smallf[8 * c + 1], va.y), 0.0f);
            float v2 = fmaxf(fmaf(kf, smallf[8 * c + 2], va.z), 0.0f);
            float v3 = fmaxf(fmaf(kf, smallf[8 * c + 3], va.w), 0.0f);
            float v4 = fmaxf(fmaf(kf, smallf[8 * c + 4], vb.x), 0.0f);
            float v5 = fmaxf(fmaf(kf, smallf[8 * c + 5], vb.y), 0.0f);
            float v6 = fmaxf(fmaf(kf, smallf[8 * c + 6], vb.z), 0.0f);
            float v7 = fmaxf(fmaf(kf, smallf[8 * c + 7], vb.w), 0.0f);
            uint4 w = make_uint4(packh2(v0, v1), packh2(v2, v3),
                                 packh2(v4, v5), packh2(v6, v7));
            uint32_t off = row * 128 + ((c ^ (row & 7)) << 4);
            *(uint4*)(sm8 + SM_A + off) = w;
        }
    }
    __syncthreads();

    // ---- layer 2: C[128,64] = Ah @ (W2h + W2l), 2 products ----
    float acc2[2][8][4];
    #pragma unroll
    for (int mt = 0; mt < 2; mt++)
        #pragma unroll
        for (int nt = 0; nt < 8; nt++)
            #pragma unroll
            for (int e = 0; e < 4; e++) acc2[mt][nt][e] = 0.0f;

    #pragma unroll
    for (int kt = 0; kt < 4; kt++) {
        uint32_t ah[2][4];
        #pragma unroll
        for (int mt = 0; mt < 2; mt++) {
            int r = rbase + mt * 16 + (lane & 15);
            uint32_t cb = kt * 32 + ((lane >> 4) << 4);
            uint32_t off = r * 128 + (cb ^ ((r & 7) << 4));
            ldmatrix4(ah[mt][0], ah[mt][1], ah[mt][2], ah[mt][3], smb + SM_A + off);
        }
        #pragma unroll
        for (int nt = 0; nt < 8; nt++) {
            int n = nt * 8 + qr;
            uint32_t byte0 = n * 128 + kt * 32 + 4 * q;
            uint32_t o0 = sw128(byte0), o1 = sw128(byte0 + 16);
            uint32_t bh0 = *(const uint32_t*)(sm8 + o0);
            uint32_t bh1 = *(const uint32_t*)(sm8 + o1);
            uint32_t bl0 = *(const uint32_t*)(sm8 + 8192 + o0);
            uint32_t bl1 = *(const uint32_t*)(sm8 + 8192 + o1);
            #pragma unroll
            for (int mt = 0; mt < 2; mt++) {
                float* d = acc2[mt][nt];
                mma16816(d[0], d[1], d[2], d[3], ah[mt][0], ah[mt][1], ah[mt][2], ah[mt][3], bh0, bh1);
                mma16816(d[0], d[1], d[2], d[3], ah[mt][0], ah[mt][1], ah[mt][2], ah[mt][3], bl0, bl1);
            }
        }
    }
    __syncthreads();   // all A reads done before overwrite

    // ---- epilogue L2: h2 = relu(C + b2) -> fp16 -> smem A ----
    #pragma unroll
    for (int mt = 0; mt < 2; mt++) {
        int r0 = rbase + mt * 16 + qr;
        #pragma unroll
        for (int nt = 0; nt < 8; nt++) {
            int cn = nt * 8 + 2 * q;
            float bb0 = smallf[64 + cn], bb1 = smallf[64 + cn + 1];
            float v0 = fmaxf(acc2[mt][nt][0] + bb0, 0.0f);
            float v1 = fmaxf(acc2[mt][nt][1] + bb1, 0.0f);
            float v2 = fmaxf(acc2[mt][nt][2] + bb0, 0.0f);
            float v3 = fmaxf(acc2[mt][nt][3] + bb1, 0.0f);
            uint32_t oa = sw128((uint32_t)(r0 * 128 + cn * 2));
            uint32_t ob = sw128((uint32_t)((r0 + 8) * 128 + cn * 2));
            *(uint32_t*)(sm8 + SM_A + oa) = packh2(v0, v1);
            *(uint32_t*)(sm8 + SM_A + ob) = packh2(v2, v3);
        }
    }
    __syncthreads();

    // ---- layer 3: C[128,32] = Ah @ (W3h + W3l) ----
    float acc3[2][4][4];
    #pragma unroll
    for (int mt = 0; mt < 2; mt++)
        #pragma unroll
        for (int nt = 0; nt < 4; nt++)
            #pragma unroll
            for (int e = 0; e < 4; e++) acc3[mt][nt][e] = 0.0f;

    #pragma unroll
    for (int kt = 0; kt < 4; kt++) {
        uint32_t ah[2][4];
        #pragma unroll
        for (int mt = 0; mt < 2; mt++) {
            int r = rbase + mt * 16 + (lane & 15);
            uint32_t cb = kt * 32 + ((lane >> 4) << 4);
            uint32_t off = r * 128 + (cb ^ ((r & 7) << 4));
            ldmatrix4(ah[mt][0], ah[mt][1], ah[mt][2], ah[mt][3], smb + SM_A + off);
        }
        #pragma unroll
        for (int nt = 0; nt < 4; nt++) {
            int n = nt * 8 + qr;
            uint32_t byte0 = n * 128 + kt * 32 + 4 * q;
            uint32_t o0 = sw128(byte0), o1 = sw128(byte0 + 16);
            uint32_t bh0 = *(const uint32_t*)(sm8 + 16384 + o0);
            uint32_t bh1 = *(const uint32_t*)(sm8 + 16384 + o1);
            uint32_t bl0 = *(const uint32_t*)(sm8 + 20480 + o0);
            uint32_t bl1 = *(const uint32_t*)(sm8 + 20480 + o1);
            #pragma unroll
            for (int mt = 0; mt < 2; mt++) {
                float* d = acc3[mt][nt];
                mma16816(d[0], d[1], d[2], d[3], ah[mt][0], ah[mt][1], ah[mt][2], ah[mt][3], bh0, bh1);
                mma16816(d[0], d[1], d[2], d[3], ah[mt][0], ah[mt][1], ah[mt][2], ah[mt][3], bl0, bl1);
            }
        }
    }

    // ---- epilogue L3: relu(C + b3) . W4, quad reduce, write ----
    #pragma unroll
    for (int mt = 0; mt < 2; mt++) {
        float sa = 0.0f, sb = 0.0f;
        #pragma unroll
        for (int nt = 0; nt < 4; nt++) {
            int cn = nt * 8 + 2 * q;
            float b0 = smallf[128 + cn], b1 = smallf[128 + cn + 1];
            float w0 = smallf[160 + cn], w1 = smallf[160 + cn + 1];
            sa = fmaf(fmaxf(acc3[mt][nt][0] + b0, 0.0f), w0, sa);
            sa = fmaf(fmaxf(acc3[mt][nt][1] + b1, 0.0f), w1, sa);
            sb = fmaf(fmaxf(acc3[mt][nt][2] + b0, 0.0f), w0, sb);
            sb = fmaf(fmaxf(acc3[mt][nt][3] + b1, 0.0f), w1, sb);
        }
        sa += __shfl_xor_sync(0xFFFFFFFFu, sa, 1);
        sa += __shfl_xor_sync(0xFFFFFFFFu, sa, 2);
        sb += __shfl_xor_sync(0xFFFFFFFFu, sb, 1);
        sb += __shfl_xor_sync(0xFFFFFFFFu, sb, 2);
        if (q == 0) {
            int ra = blockIdx.x * 128 + rbase + mt * 16 + qr;
            float b4v = smallf[192];
            if (ra < T)     out[ra]     = sa + b4v;
            if (ra + 8 < T) out[ra + 8] = sb + b4v;
        }
    }
}

// ================= launcher =================
extern "C" void kernel_launch(void* const* d_in, const int* in_sizes, int n_in,
                              void* d_out, int out_size) {
    const float* x          = (const float*)d_in[0];
    const float* h_dag      = (const float*)d_in[1];
    const float* h_glob     = (const float*)d_in[2];
    const int* ptr          = (const int*)d_in[3];
    const int* job_idx      = (const int*)d_in[4];
    const int* num_exec     = (const int*)d_in[5];
    const int* exec_aidx    = (const int*)d_in[6];
    const float* W1 = (const float*)d_in[7];
    const float* b1 = (const float*)d_in[8];
    const float* W2 = (const float*)d_in[9];
    const float* b2 = (const float*)d_in[10];
    const float* W3 = (const float*)d_in[11];
    const float* b3 = (const float*)d_in[12];
    const float* W4 = (const float*)d_in[13];
    const float* b4 = (const float*)d_in[14];
    float* out = (float*)d_out;

    int J = in_sizes[4];
    int T = in_sizes[6];

    cudaFuncSetAttribute(k_mlp_mma, cudaFuncAttributeMaxDynamicSharedMemorySize, KM_SMEM);

    int nblocks256 = (J + 255) / 256;
    int gb1 = 592;                       // persistent base1: 4 blocks/SM
    if (gb1 > (J + 7) / 8) gb1 = (J + 7) / 8;

    k_p1<<<nblocks256, 256>>>(job_idx, num_exec, J);
    k_scan<<<1, 512>>>(nblocks256);
    k_p3<<<nblocks256, 256>>>(J);
    k_base1<<<gb1, 256>>>(x, h_dag, h_glob, ptr, job_idx, W1, b1, J);
    k_wprep<<<25, 256>>>(W1, W2, b2, W3, b3, W4, b4);
    k_mlp_mma<<<(T + 127) / 128, 128, KM_SMEM>>>(exec_aidx, out, T);
}